// round 13
// baseline (speedup 1.0000x reference)
#include <cuda_runtime.h>

typedef unsigned long long ull;

// ---------------- f32x2 helpers ----------------
__device__ __forceinline__ ull pk2(float lo, float hi) {
    ull r;
    asm("mov.b64 %0, {%1, %2};" : "=l"(r) : "r"(__float_as_uint(lo)), "r"(__float_as_uint(hi)));
    return r;
}
__device__ __forceinline__ ull bc2(float x) { return pk2(x, x); }
__device__ __forceinline__ void upk2(ull v, float& lo, float& hi) {
    unsigned a, b;
    asm("mov.b64 {%0, %1}, %2;" : "=r"(a), "=r"(b) : "l"(v));
    lo = __uint_as_float(a); hi = __uint_as_float(b);
}
__device__ __forceinline__ ull sw2(ull v) {
    unsigned a, b;
    asm("mov.b64 {%0, %1}, %2;" : "=r"(a), "=r"(b) : "l"(v));
    ull r;
    asm("mov.b64 %0, {%1, %2};" : "=l"(r) : "r"(b), "r"(a));
    return r;
}
__device__ __forceinline__ ull f2fma(ull a, ull b, ull c) {
    ull d;
    asm("fma.rn.f32x2 %0, %1, %2, %3;" : "=l"(d) : "l"(a), "l"(b), "l"(c));
    return d;
}
__device__ __forceinline__ ull f2mul(ull a, ull b) {
    ull d;
    asm("mul.rn.f32x2 %0, %1, %2;" : "=l"(d) : "l"(a), "l"(b));
    return d;
}
__device__ __forceinline__ ull f2add(ull a, ull b) {
    ull d;
    asm("add.rn.f32x2 %0, %1, %2;" : "=l"(d) : "l"(a), "l"(b));
    return d;
}
__device__ __forceinline__ ull shx(ull v, int m)  { return __shfl_xor_sync(0xFFFFFFFFu, v, m); }
__device__ __forceinline__ ull sh4(ull v, int s)  { return __shfl_sync(0xFFFFFFFFu, v, s, 4); }
__device__ __forceinline__ ull shd4(ull v)        { return __shfl_down_sync(0xFFFFFFFFu, v, 1, 4); }
__device__ __forceinline__ float hsum(ull v) { float a, b; upk2(v, a, b); return a + b; }
__device__ __forceinline__ float hdif(ull v) { float a, b; upk2(v, a, b); return a - b; }

// Top row of U = Rz(a4) Ry(a3) Rz(a2) Ry(a1) Rz(a0) M0, M0=[[m00,m01],[m01,-m00]].
// Full U recoverable: det(U)=-1 -> u10=conj(u01), u11=-conj(u00).
__device__ __forceinline__ void buildTop(float m00, float m01,
                                         float a0, float a1, float a2, float a3, float a4,
                                         float& r00, float& i00, float& r01, float& i01) {
    float c, s;
    __sincosf(0.5f * a0, &s, &c);
    float u00r = m00 * c,  u00i = -m00 * s;
    float u01r = m01 * c,  u01i = -m01 * s;
    float u10r = m01 * c,  u10i =  m01 * s;
    float u11r = -m00 * c, u11i = -m00 * s;
    __sincosf(0.5f * a1, &s, &c);
    float n00r = c*u00r - s*u10r, n00i = c*u00i - s*u10i;
    float n01r = c*u01r - s*u11r, n01i = c*u01i - s*u11i;
    float n10r = s*u00r + c*u10r, n10i = s*u00i + c*u10i;
    float n11r = s*u01r + c*u11r, n11i = s*u01i + c*u11i;
    __sincosf(0.5f * a2, &s, &c);
    u00r = c*n00r + s*n00i; u00i = c*n00i - s*n00r;
    u01r = c*n01r + s*n01i; u01i = c*n01i - s*n01r;
    u10r = c*n10r - s*n10i; u10i = c*n10i + s*n10r;
    u11r = c*n11r - s*n11i; u11i = c*n11i + s*n11r;
    __sincosf(0.5f * a3, &s, &c);
    n00r = c*u00r - s*u10r; n00i = c*u00i - s*u10i;
    n01r = c*u01r - s*u11r; n01i = c*u01i - s*u11i;
    __sincosf(0.5f * a4, &s, &c);
    r00 = c*n00r + s*n00i; i00 = c*n00i - s*n00r;
    r01 = c*n01r + s*n01i; i01 = c*n01i - s*n01r;
}

// ---------------- kernel: 4 lanes per element ----------------
// Lane sub holds amps with (bit3,bit2)=(sub>>1, sub&1); within lane amps by (b1,b0):
//   T0 = (A00, A11), T1 = (A01, A10)

__global__ void __launch_bounds__(128, 4)
multi_encoding_kernel(const float* __restrict__ x,
                      const float* __restrict__ crz_theta,
                      const float* __restrict__ ry_theta,
                      const float* __restrict__ fc1_w,
                      const float* __restrict__ fc1_b,
                      const float* __restrict__ fc2_w,
                      const float* __restrict__ fc2_b,
                      float* __restrict__ out,
                      int nB)
{
    const int t = blockIdx.x * blockDim.x + threadIdx.x;
    const int e = t >> 2;
    const int sub = t & 3;
    if (e >= nB) return;
    const int l1 = (sub >> 1) & 1;   // amp bit3 (qubit 0)
    const int l0 = sub & 1;          // amp bit2 (qubit 1)
    const float* img = x + e * 784;

    const float rh = 0.70710678118654752f;

    // fixed Ry fold + rotated observables
    const float theta = ry_theta[0];
    const float rc = cosf(0.5f * theta), rs = sinf(0.5f * theta);
    const float m00ry = rh * (rc + rs);
    const float m01ry = rh * (rc - rs);
    const float cth  = cosf(theta);
    const float sth  = sinf(theta);
    const float nsin  = -sth;
    const float nsth2 = -2.0f * sth;
    const float cths0 = l1 ? -cth : cth;
    const float cths1 = l0 ? -cth : cth;
    const float sg1 = l1 ? -1.f : 1.f;
    const float sg0 = l0 ? -1.f : 1.f;

    // CRZ diagonal per-lane packed constants: diag = exp(i*thc*S)
    const float thc = 0.5f * crz_theta[0];
    const float c1 = cosf(thc),       s1 = sinf(thc);
    const float c2 = cosf(2.f * thc), s2 = sinf(2.f * thc);
    const float c4 = cosf(4.f * thc), s4 = sinf(4.f * thc);
    ull dr0, di0, ndi0, dr1, di1, ndi1;
    if (sub == 0) {
        dr0 = pk2(1.f, 1.f); di0 = pk2(0.f, 0.f);   ndi0 = pk2(0.f, 0.f);
        dr1 = bc2(c1);       di1 = pk2(-s1, -s1);   ndi1 = pk2(s1, s1);
    } else if (sub == 1) {
        dr0 = bc2(c1);       di0 = pk2(-s1, s1);    ndi0 = pk2(s1, -s1);
        dr1 = pk2(c2, 1.f);  di1 = pk2(-s2, 0.f);   ndi1 = pk2(s2, 0.f);
    } else if (sub == 2) {
        dr0 = bc2(c1);       di0 = pk2(-s1, s1);    ndi0 = pk2(s1, -s1);
        dr1 = pk2(1.f, c2);  di1 = pk2(0.f, -s2);   ndi1 = pk2(0.f, s2);
    } else {
        dr0 = pk2(1.f, c4);  di0 = pk2(0.f, s4);    ndi0 = pk2(0.f, -s4);
        dr1 = bc2(c1);       di1 = pk2(s1, s1);     ndi1 = pk2(-s1, -s1);
    }
    const ull MM = bc2(-1.f);

    // angle indices for this lane
    int km[5];
#pragma unroll
    for (int m = 0; m < 5; m++) km[m] = 5 * sub + m;

    // state |0000>
    ull R0 = pk2(sub == 0 ? 1.f : 0.f, 0.f), R1 = 0ull;
    ull I0 = 0ull, I1 = 0ull;

    const float* fc1base = fc1_w + (sub * 5) * 784;
    float h1a[5];
#pragma unroll
    for (int o = 0; o < 5; o++) h1a[o] = 0.f;

    float m00 = rh, m01 = rh;
    float e0part = 0.f, e1p = 0.f, e2p = 0.f, e3p = 0.f;

    int win = 0;
    for (int iw = 0; iw < 14; iw++) {
        const float* wq = img + (iw * 2) * 28;
        for (int jw = 0; jw < 14; jw++, win++) {
            const float* wp = wq + jw * 2;

            // ---- cooperative angle loads: 2 x LDG.64 + 2 x SHFL per lane ----
            // pool float p[i] = f[4*sub + i] (i=0..3 own, 4..7 neighbor lane sub+1);
            // angle m = p[sub+m], zeroed when km[m] >= lim (compacted edge windows).
            float a0, a1, a2, a3, a4;
            {
                int offA, offB, lim;
                if (jw < 13) {
                    int r = (iw < 13) ? sub : min(sub, 1);   // clamp for h=2
                    offA = r * 28;
                    offB = offA + 2;
                    lim  = (iw < 13) ? 16 : 8;
                } else {
                    // compact map: f_k = mem[k>>1][k&1]; lane loads rows 2sub, 2sub+1
                    int hh = (iw < 13) ? 4 : 2;
                    int rA = min(2 * sub,     hh - 1);
                    int rB = min(2 * sub + 1, hh - 1);
                    offA = rA * 28;
                    offB = rB * 28;
                    lim  = 2 * hh;
                }
                float2 LA = *reinterpret_cast<const float2*>(wp + offA);
                float2 LB = *reinterpret_cast<const float2*>(wp + offB);
                ull RA = pk2(LA.x, LA.y);
                ull RB = pk2(LB.x, LB.y);
                ull NA = shd4(RA);
                ull NB = shd4(RB);
                float lo, hi;
                ull W;
                // m=0: i=sub in 0..3 -> word 0/1
                W = (sub < 2) ? RA : RB;
                upk2(W, lo, hi); a0 = (sub & 1) ? hi : lo;
                // m=1: i in 1..4 -> word 0/1/2
                W = (sub + 1 < 4) ? ((sub + 1 < 2) ? RA : RB) : NA;
                upk2(W, lo, hi); a1 = ((sub + 1) & 1) ? hi : lo;
                // m=2: i in 2..5 -> word 1/2
                W = (sub + 2 < 4) ? RB : NA;
                upk2(W, lo, hi); a2 = (sub & 1) ? hi : lo;
                // m=3: i in 3..6 -> word 1/2/3
                W = (sub + 3 < 4) ? RB : ((sub + 3 < 6) ? NA : NB);
                upk2(W, lo, hi); a3 = ((sub + 1) & 1) ? hi : lo;
                // m=4: i in 4..7 -> word 2/3
                W = (sub + 4 < 6) ? NA : NB;
                upk2(W, lo, hi); a4 = (sub & 1) ? hi : lo;
                a0 = (km[0] < lim) ? a0 : 0.f;
                a1 = (km[1] < lim) ? a1 : 0.f;
                a2 = (km[2] < lim) ? a2 : 0.f;
                a3 = (km[3] < lim) ? a3 : 0.f;
                a4 = (km[4] < lim) ? a4 : 0.f;
            }

            // ---- build own gate's top row (lane3: zero angles -> Rz(f15)*M0) ----
            float br00, bi00, br01, bi01;
            buildTop(m00, m01, a0, a1, a2, a3, a4, br00, bi00, br01, bi01);
            ull E0 = pk2(br00, bi00), E1 = pk2(br01, bi01);

            // ---- exchange: top rows of all 4 gates ----
            ull G00 = sh4(E0, 0), G01 = sh4(E1, 0);
            ull G10 = sh4(E0, 1), G11 = sh4(E1, 1);
            ull G20 = sh4(E0, 2), G21 = sh4(E1, 2);
            ull G30 = sh4(E0, 3), G31 = sh4(E1, 3);

            // ---- qubit 0 (bit3, xor 2): shuffle state (also serves prev X0) ----
            ull Rp0 = shx(R0, 2), Rp1 = shx(R1, 2);
            ull Ip0 = shx(I0, 2), Ip1 = shx(I1, 2);

            if (win > 0) {   // complete prev window's e0, reduce, accumulate fc1
                ull d0 = f2add(f2fma(I0, Ip0, f2mul(R0, Rp0)),
                               f2fma(I1, Ip1, f2mul(R1, Rp1)));
                float e0p = fmaf(nsin, hsum(d0), e0part);
                ull E01 = pk2(e0p, e1p), E23 = pk2(e2p, e3p);
                E01 = f2add(E01, shx(E01, 1)); E23 = f2add(E23, shx(E23, 1));
                E01 = f2add(E01, shx(E01, 2)); E23 = f2add(E23, shx(E23, 2));
                float ee0, ee1, ee2, ee3;
                upk2(E01, ee0, ee1); upk2(E23, ee2, ee3);
                const float* ww = fc1base + (win - 1) * 4;
#pragma unroll
                for (int o = 0; o < 5; o++) {
                    float4 wv = __ldg(reinterpret_cast<const float4*>(ww + o * 784));
                    h1a[o] = fmaf(ee0, wv.x, fmaf(ee1, wv.y, fmaf(ee2, wv.z, fmaf(ee3, wv.w, h1a[o]))));
                }
            }

            // apply qubit-0 gate (one-sided; coeffs from lane0's top row)
            {
                float r00, i00, r01, i01;
                upk2(G00, r00, i00); upk2(G01, r01, i01);
                float csr = sg1 * r00;
                float coi = sg1 * i01;
                ull CSR = bc2(csr), CSI = bc2(i00), CNSI = bc2(-i00);
                ull COR = bc2(r01), COI = bc2(coi), CNOI = bc2(-coi);
                ull nr0 = f2fma(CNOI, Ip0, f2fma(COR, Rp0, f2fma(CNSI, I0, f2mul(CSR, R0))));
                ull ni0 = f2fma(COI, Rp0, f2fma(COR, Ip0, f2fma(CSI, R0, f2mul(CSR, I0))));
                ull nr1 = f2fma(CNOI, Ip1, f2fma(COR, Rp1, f2fma(CNSI, I1, f2mul(CSR, R1))));
                ull ni1 = f2fma(COI, Rp1, f2fma(COR, Ip1, f2fma(CSI, R1, f2mul(CSR, I1))));
                R0 = nr0; I0 = ni0; R1 = nr1; I1 = ni1;
            }
            // ---- qubit 1 (bit2, xor 1): one-sided cross-lane ----
            {
                float r00, i00, r01, i01;
                upk2(G10, r00, i00); upk2(G11, r01, i01);
                float csr = sg0 * r00;
                float coi = sg0 * i01;
                ull CSR = bc2(csr), CSI = bc2(i00), CNSI = bc2(-i00);
                ull COR = bc2(r01), COI = bc2(coi), CNOI = bc2(-coi);
                ull Rq0 = shx(R0, 1), Rq1 = shx(R1, 1);
                ull Iq0 = shx(I0, 1), Iq1 = shx(I1, 1);
                ull nr0 = f2fma(CNOI, Iq0, f2fma(COR, Rq0, f2fma(CNSI, I0, f2mul(CSR, R0))));
                ull ni0 = f2fma(COI, Rq0, f2fma(COR, Iq0, f2fma(CSI, R0, f2mul(CSR, I0))));
                ull nr1 = f2fma(CNOI, Iq1, f2fma(COR, Rq1, f2fma(CNSI, I1, f2mul(CSR, R1))));
                ull ni1 = f2fma(COI, Rq1, f2fma(COR, Iq1, f2fma(CSI, R1, f2mul(CSR, I1))));
                R0 = nr0; I0 = ni0; R1 = nr1; I1 = ni1;
            }
            // ---- qubit 2 (bit1, in-lane): A=T0, B=sw2(T1) ----
            {
                float r00, i00, r01, i01;
                upk2(G20, r00, i00); upk2(G21, r01, i01);
                ull P1 = pk2(r00, -r00), P5 = pk2(-r00, r00);
                ull P2 = bc2(i00), P2n = bc2(-i00);
                ull P3 = bc2(r01);
                ull P4 = pk2(i01, -i01), P4n = pk2(-i01, i01);
                ull Br = sw2(R1), Bi = sw2(I1);
                ull pr = f2fma(P4n, Bi, f2fma(P3, Br, f2fma(P2n, I0, f2mul(P1, R0))));
                ull pi = f2fma(P4,  Br, f2fma(P3, Bi, f2fma(P2,  R0, f2mul(P1, I0))));
                ull qr = f2fma(P2n, Bi, f2fma(P5, Br, f2fma(P4,  I0, f2mul(P3, R0))));
                ull qi = f2fma(P2,  Br, f2fma(P5, Bi, f2fma(P4n, R0, f2mul(P3, I0))));
                R0 = pr; I0 = pi; R1 = sw2(qr); I1 = sw2(qi);
            }
            // ---- qubit 3 (bit0, in-lane): A=T0, B=T1 ----
            {
                float r00, i00, r01, i01;
                upk2(G30, r00, i00); upk2(G31, r01, i01);
                ull P1 = pk2(r00, -r00), P5 = pk2(-r00, r00);
                ull P2 = bc2(i00), P2n = bc2(-i00);
                ull P3 = bc2(r01);
                ull P4 = pk2(i01, -i01), P4n = pk2(-i01, i01);
                ull pr = f2fma(P4n, I1, f2fma(P3, R1, f2fma(P2n, I0, f2mul(P1, R0))));
                ull pi = f2fma(P4,  R1, f2fma(P3, I1, f2fma(P2,  R0, f2mul(P1, I0))));
                ull qr = f2fma(P2n, I1, f2fma(P5, R1, f2fma(P4,  I0, f2mul(P3, R0))));
                ull qi = f2fma(P2,  R1, f2fma(P5, I1, f2fma(P4n, R0, f2mul(P3, I0))));
                R0 = pr; I0 = pi; R1 = qr; I1 = qi;
            }

            // ---- CRZ diagonal ----
            {
                ull nr = f2fma(ndi0, I0, f2mul(dr0, R0));
                ull ni = f2fma(di0,  R0, f2mul(dr0, I0));
                R0 = nr; I0 = ni;
                nr = f2fma(ndi1, I1, f2mul(dr1, R1));
                ni = f2fma(di1,  R1, f2mul(dr1, I1));
                R1 = nr; I1 = ni;
            }

            // ---- measurement partials (rotated observables on pre-Ry state) ----
            {
                ull p0 = f2fma(I0, I0, f2mul(R0, R0));
                ull p1 = f2fma(I1, I1, f2mul(R1, R1));
                ull s01 = f2add(p0, p1);
                ull d01 = f2fma(MM, p1, p0);
                float Pm  = hsum(s01);
                float z2p = hdif(s01);
                float z3p = hdif(d01);
                ull x2v = f2fma(I0, sw2(I1), f2mul(R0, sw2(R1)));
                ull x3v = f2fma(I0, I1, f2mul(R0, R1));
                ull Rq0 = shx(R0, 1), Rq1 = shx(R1, 1);
                ull Iq0 = shx(I0, 1), Iq1 = shx(I1, 1);
                ull x1v = f2add(f2fma(I0, Iq0, f2mul(R0, Rq0)),
                                f2fma(I1, Iq1, f2mul(R1, Rq1)));
                e0part = cths0 * Pm;
                e1p = fmaf(nsin,  hsum(x1v), cths1 * Pm);
                e2p = fmaf(nsth2, hsum(x2v), cth * z2p);
                e3p = fmaf(nsth2, hsum(x3v), cth * z3p);
            }

            m00 = m00ry; m01 = m01ry;
        }
    }

    // ---- tail: finish window 195 ----
    {
        ull Rp0 = shx(R0, 2), Rp1 = shx(R1, 2);
        ull Ip0 = shx(I0, 2), Ip1 = shx(I1, 2);
        ull d0 = f2add(f2fma(I0, Ip0, f2mul(R0, Rp0)),
                       f2fma(I1, Ip1, f2mul(R1, Rp1)));
        float e0p = fmaf(nsin, hsum(d0), e0part);
        ull E01 = pk2(e0p, e1p), E23 = pk2(e2p, e3p);
        E01 = f2add(E01, shx(E01, 1)); E23 = f2add(E23, shx(E23, 1));
        E01 = f2add(E01, shx(E01, 2)); E23 = f2add(E23, shx(E23, 2));
        float ee0, ee1, ee2, ee3;
        upk2(E01, ee0, ee1); upk2(E23, ee2, ee3);
        const float* ww = fc1base + 195 * 4;
#pragma unroll
        for (int o = 0; o < 5; o++) {
            float4 wv = __ldg(reinterpret_cast<const float4*>(ww + o * 784));
            h1a[o] = fmaf(ee0, wv.x, fmaf(ee1, wv.y, fmaf(ee2, wv.z, fmaf(ee3, wv.w, h1a[o]))));
        }
    }

    // ---- epilogue: bias + leaky relu + fc2, reduce over quad ----
    float a0p = 0.f, a1p = 0.f;
#pragma unroll
    for (int o = 0; o < 5; o++) {
        int oo = sub * 5 + o;
        float hh = h1a[o] + fc1_b[oo];
        hh = hh > 0.f ? hh : 0.1f * hh;
        a0p = fmaf(fc2_w[oo],      hh, a0p);
        a1p = fmaf(fc2_w[20 + oo], hh, a1p);
    }
    ull A = pk2(a0p, a1p);
    A = f2add(A, shx(A, 1));
    A = f2add(A, shx(A, 2));
    if (sub == 0) {
        float aa0, aa1;
        upk2(A, aa0, aa1);
        out[2 * e + 0] = aa0 + fc2_b[0];
        out[2 * e + 1] = aa1 + fc2_b[1];
    }
}

extern "C" void kernel_launch(void* const* d_in, const int* in_sizes, int n_in,
                              void* d_out, int out_size) {
    const float* x     = (const float*)d_in[0];
    const float* crz   = (const float*)d_in[1];
    const float* ry    = (const float*)d_in[2];
    const float* fc1_w = (const float*)d_in[3];
    const float* fc1_b = (const float*)d_in[4];
    const float* fc2_w = (const float*)d_in[5];
    const float* fc2_b = (const float*)d_in[6];
    float* out = (float*)d_out;

    int nB = in_sizes[0] / 784;              // 16384
    int nThreads = nB * 4;                   // 4 lanes per element
    const int TPB = 128;
    int blocks = (nThreads + TPB - 1) / TPB; // 512 blocks -> 2048 warps

    multi_encoding_kernel<<<blocks, TPB>>>(x, crz, ry, fc1_w, fc1_b, fc2_w, fc2_b, out, nB);
}